// round 4
// baseline (speedup 1.0000x reference)
#include <cuda_runtime.h>
#include <cuda_bf16.h>
#include <math.h>

// ---------------------------------------------------------------------------
// Problem constants
// ---------------------------------------------------------------------------
#define B_TOT   2048
#define NTOK    98
#define CDIM    256
#define NHEADS  8
#define DH      32
#define NWIN    64
#define MROWS   (B_TOT * NTOK)          // 200704
#define QKV_N   (3 * CDIM)              // 768
#define SCALE   0.17677669529663687f    // 32^-0.5

// ---------------------------------------------------------------------------
// Scratch (static device globals -- no allocation allowed)
// ---------------------------------------------------------------------------
__device__ float g_qkv[(size_t)MROWS * QKV_N];       // 616 MB
__device__ float g_attn_out[(size_t)MROWS * CDIM];   // 205 MB
__device__ float g_bias[NHEADS * NTOK * NTOK];       // 300 KB

// ---------------------------------------------------------------------------
// Kernel 1: expand relative-position bias table -> [H, 98, 98]
// window (2,7,7): idx = (dd+1)*169 + (dh+6)*13 + (dw+6)
// ---------------------------------------------------------------------------
__global__ void wa3d_bias_kernel(const float* __restrict__ bias_table) {
    int i = blockIdx.x;          // row 0..97
    int m = threadIdx.x;         // col
    if (m >= NTOK) return;
    int di = i / 49, hi = (i / 7) % 7, wi = i % 7;
    int dm = m / 49, hm = (m / 7) % 7, wm = m % 7;
    int idx = (di - dm + 1) * 169 + (hi - hm + 6) * 13 + (wi - wm + 6);
#pragma unroll
    for (int h = 0; h < NHEADS; ++h)
        g_bias[h * (NTOK * NTOK) + i * NTOK + m] = bias_table[idx * NHEADS + h];
}

// ---------------------------------------------------------------------------
// Kernel 2/4: 128x128x8 SGEMM, 256 threads, 8x8 per thread, float4 everywhere.
// All dims divide tiles exactly for this problem (no bounds checks).
// C = A[M,K] * B[K,N] (+ bias[col] if HAS_BIAS)
// ---------------------------------------------------------------------------
template<bool HAS_BIAS>
__global__ void __launch_bounds__(256)
wa3d_sgemm128(const float* __restrict__ A, const float* __restrict__ B,
              const float* __restrict__ bias, float* __restrict__ C,
              int M, int N, int K)
{
    __shared__ float As[8][128];   // transposed A tile
    __shared__ float Bs[8][128];

    const int tid   = threadIdx.x;
    const int a_row = tid >> 1;          // 0..127
    const int a_col = (tid & 1) << 2;    // 0 or 4
    const int b_row = tid >> 5;          // 0..7
    const int b_col = (tid & 31) << 2;   // 0..124
    const int tx    = tid & 15;
    const int ty    = tid >> 4;

    const float* Ap = A + (size_t)(blockIdx.y * 128 + a_row) * K + a_col;
    const float* Bp = B + (size_t)b_row * N + blockIdx.x * 128 + b_col;

    float acc[8][8];
#pragma unroll
    for (int i = 0; i < 8; ++i)
#pragma unroll
        for (int j = 0; j < 8; ++j) acc[i][j] = 0.f;

    for (int k0 = 0; k0 < K; k0 += 8) {
        float4 a = *(const float4*)(Ap + k0);
        float4 b = *(const float4*)(Bp + (size_t)k0 * N);
        As[a_col + 0][a_row] = a.x;
        As[a_col + 1][a_row] = a.y;
        As[a_col + 2][a_row] = a.z;
        As[a_col + 3][a_row] = a.w;
        *(float4*)&Bs[b_row][b_col] = b;
        __syncthreads();
#pragma unroll
        for (int kk = 0; kk < 8; ++kk) {
            float ar[8], br[8];
            *(float4*)(ar)     = *(const float4*)&As[kk][ty * 8];
            *(float4*)(ar + 4) = *(const float4*)&As[kk][ty * 8 + 4];
            *(float4*)(br)     = *(const float4*)&Bs[kk][tx * 8];
            *(float4*)(br + 4) = *(const float4*)&Bs[kk][tx * 8 + 4];
#pragma unroll
            for (int i = 0; i < 8; ++i)
#pragma unroll
                for (int j = 0; j < 8; ++j)
                    acc[i][j] = fmaf(ar[i], br[j], acc[i][j]);
        }
        __syncthreads();
    }

    const int row0 = blockIdx.y * 128 + ty * 8;
    const int col0 = blockIdx.x * 128 + tx * 8;
    float bv[8];
    if (HAS_BIAS) {
#pragma unroll
        for (int j = 0; j < 8; ++j) bv[j] = bias[col0 + j];
    }
#pragma unroll
    for (int i = 0; i < 8; ++i) {
        float4 o0, o1;
        if (HAS_BIAS) {
            o0 = make_float4(acc[i][0] + bv[0], acc[i][1] + bv[1],
                             acc[i][2] + bv[2], acc[i][3] + bv[3]);
            o1 = make_float4(acc[i][4] + bv[4], acc[i][5] + bv[5],
                             acc[i][6] + bv[6], acc[i][7] + bv[7]);
        } else {
            o0 = make_float4(acc[i][0], acc[i][1], acc[i][2], acc[i][3]);
            o1 = make_float4(acc[i][4], acc[i][5], acc[i][6], acc[i][7]);
        }
        float* cp = C + (size_t)(row0 + i) * N + col0;
        *(float4*)(cp)     = o0;
        *(float4*)(cp + 4) = o1;
    }
}

// ---------------------------------------------------------------------------
// Kernel 3: attention. One CTA per (b, h). 128 threads.
// smem: scores[98][99] (pre-seeded with bias+mask, coalesced), k/v as float4
// rows. Row-per-thread dot with q in registers, k/v reads are warp-broadcast.
// ---------------------------------------------------------------------------
#define SC_PITCH 99
#define SC_FLOATS 9704                       // 98*99=9702, padded to 16B mult
#define ATTN_SMEM_BYTES ((SC_FLOATS + 2 * NTOK * DH) * 4)   // 63904 B

__global__ void __launch_bounds__(128)
wa3d_attention_kernel(const float* __restrict__ mask)
{
    extern __shared__ float smem[];
    float*  sc = smem;                                   // [98][99]
    float4* k4 = (float4*)(smem + SC_FLOATS);            // [98][8]
    float4* v4 = k4 + NTOK * (DH / 4);                   // [98][8]

    const int bh = blockIdx.x;
    const int b  = bh >> 3;          // /8
    const int h  = bh & 7;
    const int w  = b & (NWIN - 1);   // b % 64
    const int tid = threadIdx.x;

    // ---- cooperative loads --------------------------------------------
    const size_t row_base = (size_t)b * NTOK * QKV_N + h * DH;
    // k, v tiles (float4 rows, coalesced across lanes)
    for (int idx = tid; idx < NTOK * (DH / 4); idx += 128) {
        int r = idx >> 3, c = idx & 7;
        const float* kp = g_qkv + row_base + (size_t)r * QKV_N + CDIM + c * 4;
        const float* vp = g_qkv + row_base + (size_t)r * QKV_N + 2 * CDIM + c * 4;
        k4[idx] = *(const float4*)kp;
        v4[idx] = *(const float4*)vp;
    }
    // bias + mask pre-seed of scores (coalesced linear reads)
    const float* bp = g_bias + h * (NTOK * NTOK);
    const float* mp = mask + (size_t)w * (NTOK * NTOK);
    for (int idx = tid; idx < NTOK * NTOK; idx += 128) {
        int i = idx / NTOK, m = idx - i * NTOK;
        sc[i * SC_PITCH + m] = bp[idx] + mp[idx];
    }
    __syncthreads();

    if (tid < NTOK) {
        const int i = tid;

        // ---- q row into registers ------------------------------------
        float4 q[8];
        const float* qp = g_qkv + row_base + (size_t)i * QKV_N;
#pragma unroll
        for (int c = 0; c < 8; ++c) q[c] = *(const float4*)(qp + c * 4);

        // ---- scores = q.kT * scale + (bias+mask) ---------------------
        float* srow = sc + i * SC_PITCH;
        for (int m = 0; m < NTOK; ++m) {
            const float4* kr = k4 + m * 8;
            float s = 0.f;
#pragma unroll
            for (int c = 0; c < 8; ++c) {
                float4 kv = kr[c];
                s = fmaf(q[c].x, kv.x, s);
                s = fmaf(q[c].y, kv.y, s);
                s = fmaf(q[c].z, kv.z, s);
                s = fmaf(q[c].w, kv.w, s);
            }
            srow[m] = fmaf(s, SCALE, srow[m]);
        }

        // ---- softmax --------------------------------------------------
        float mx = -1e30f;
        for (int m = 0; m < NTOK; ++m) mx = fmaxf(mx, srow[m]);
        float sum = 0.f;
        for (int m = 0; m < NTOK; ++m) {
            float e = __expf(srow[m] - mx);
            srow[m] = e;
            sum += e;
        }
        const float inv = 1.f / sum;

        // ---- O = P.V --------------------------------------------------
        float4 o[8];
#pragma unroll
        for (int c = 0; c < 8; ++c) o[c] = make_float4(0.f, 0.f, 0.f, 0.f);
        for (int m = 0; m < NTOK; ++m) {
            const float p = srow[m];
            const float4* vr = v4 + m * 8;
#pragma unroll
            for (int c = 0; c < 8; ++c) {
                float4 vv = vr[c];
                o[c].x = fmaf(p, vv.x, o[c].x);
                o[c].y = fmaf(p, vv.y, o[c].y);
                o[c].z = fmaf(p, vv.z, o[c].z);
                o[c].w = fmaf(p, vv.w, o[c].w);
            }
        }
        float* op = g_attn_out + (size_t)(b * NTOK + i) * CDIM + h * DH;
#pragma unroll
        for (int c = 0; c < 8; ++c) {
            float4 ov = make_float4(o[c].x * inv, o[c].y * inv,
                                    o[c].z * inv, o[c].w * inv);
            *(float4*)(op + c * 4) = ov;
        }
    }
}

// ---------------------------------------------------------------------------
// Launch
// ---------------------------------------------------------------------------
extern "C" void kernel_launch(void* const* d_in, const int* in_sizes, int n_in,
                              void* d_out, int out_size)
{
    const float* x          = (const float*)d_in[0];
    const float* mask       = (const float*)d_in[1];
    const float* qkv_w      = (const float*)d_in[2];
    const float* proj_w     = (const float*)d_in[3];
    const float* proj_b     = (const float*)d_in[4];
    const float* bias_table = (const float*)d_in[5];
    float* out = (float*)d_out;

    float* qkv;      cudaGetSymbolAddress((void**)&qkv, g_qkv);
    float* attn_out; cudaGetSymbolAddress((void**)&attn_out, g_attn_out);

    // 1. bias table expansion
    wa3d_bias_kernel<<<NTOK, 128>>>(bias_table);

    // 2. qkv = x @ qkv_w   [200704,256]x[256,768]
    {
        dim3 grid(QKV_N / 128, MROWS / 128);
        wa3d_sgemm128<false><<<grid, 256>>>(x, qkv_w, nullptr, qkv,
                                            MROWS, QKV_N, CDIM);
    }

    // 3. attention
    cudaFuncSetAttribute(wa3d_attention_kernel,
                         cudaFuncAttributeMaxDynamicSharedMemorySize,
                         ATTN_SMEM_BYTES);
    wa3d_attention_kernel<<<B_TOT * NHEADS, 128, ATTN_SMEM_BYTES>>>(mask);

    // 4. out = attn_out @ proj_w + proj_b   [200704,256]x[256,256]
    {
        dim3 grid(CDIM / 128, MROWS / 128);
        wa3d_sgemm128<true><<<grid, 256>>>(attn_out, proj_w, proj_b, out,
                                           MROWS, CDIM, CDIM);
    }
}

// round 7
// speedup vs baseline: 1.5312x; 1.5312x over previous
#include <cuda_runtime.h>
#include <cuda_bf16.h>
#include <math.h>
#include <stdint.h>

// ---------------------------------------------------------------------------
// Problem constants
// ---------------------------------------------------------------------------
#define B_TOT   2048
#define NTOK    98
#define CDIM    256
#define NHEADS  8
#define DH      32
#define NWIN    64
#define MROWS   (B_TOT * NTOK)          // 200704
#define QKV_N   (3 * CDIM)              // 768
#define SCALE   0.17677669529663687f    // 32^-0.5

// ---------------------------------------------------------------------------
// Scratch (static device globals -- no allocation allowed)
// ---------------------------------------------------------------------------
__device__ float          g_qkv[(size_t)MROWS * QKV_N];      // 616 MB fp32
__device__ __nv_bfloat16  g_xhi[(size_t)MROWS * CDIM];
__device__ __nv_bfloat16  g_xlo[(size_t)MROWS * CDIM];
__device__ __nv_bfloat16  g_aohi[(size_t)MROWS * CDIM];
__device__ __nv_bfloat16  g_aolo[(size_t)MROWS * CDIM];
__device__ __nv_bfloat16  g_wqkv_hi[QKV_N * CDIM];           // B layout [N][K]
__device__ __nv_bfloat16  g_wqkv_lo[QKV_N * CDIM];
__device__ __nv_bfloat16  g_wproj_hi[CDIM * CDIM];
__device__ __nv_bfloat16  g_wproj_lo[CDIM * CDIM];
__device__ float          g_bias[NHEADS * NTOK * NTOK];

// ---------------------------------------------------------------------------
// fp32 -> (hi, lo) bf16 split
// ---------------------------------------------------------------------------
__device__ __forceinline__ void f32_split(float v, __nv_bfloat16& h, __nv_bfloat16& l) {
    h = __float2bfloat16(v);
    l = __float2bfloat16(v - __bfloat162float(h));
}

// ---------------------------------------------------------------------------
// Kernel: bias table expansion -> [H, 98, 98]
// ---------------------------------------------------------------------------
__global__ void wa3d_bias_kernel(const float* __restrict__ bias_table) {
    int i = blockIdx.x;
    int m = threadIdx.x;
    if (m >= NTOK) return;
    int di = i / 49, hi = (i / 7) % 7, wi = i % 7;
    int dm = m / 49, hm = (m / 7) % 7, wm = m % 7;
    int idx = (di - dm + 1) * 169 + (hi - hm + 6) * 13 + (wi - wm + 6);
#pragma unroll
    for (int h = 0; h < NHEADS; ++h)
        g_bias[h * (NTOK * NTOK) + i * NTOK + m] = bias_table[idx * NHEADS + h];
}

// ---------------------------------------------------------------------------
// Kernel: split activations fp32 -> hi/lo bf16 (vectorized by 4)
// ---------------------------------------------------------------------------
__global__ void wa3d_cvt_split4(const float4* __restrict__ src,
                                uint2* __restrict__ hi, uint2* __restrict__ lo,
                                int n4) {
    int i = blockIdx.x * blockDim.x + threadIdx.x;
    if (i >= n4) return;
    float4 v = src[i];
    union { __nv_bfloat16 b[4]; uint2 u; } H, L;
    f32_split(v.x, H.b[0], L.b[0]);
    f32_split(v.y, H.b[1], L.b[1]);
    f32_split(v.z, H.b[2], L.b[2]);
    f32_split(v.w, H.b[3], L.b[3]);
    hi[i] = H.u;
    lo[i] = L.u;
}

// ---------------------------------------------------------------------------
// Kernel: transpose + split weights  w[K=256][N] -> B[N][256] hi/lo bf16
// ---------------------------------------------------------------------------
__global__ void wa3d_cvt_w(const float* __restrict__ w,
                           __nv_bfloat16* __restrict__ bhi,
                           __nv_bfloat16* __restrict__ blo, int N) {
    int n = blockIdx.x;
    int k = threadIdx.x;          // 0..255
    float v = w[(size_t)k * N + n];
    __nv_bfloat16 h, l;
    f32_split(v, h, l);
    bhi[(size_t)n * CDIM + k] = h;
    blo[(size_t)n * CDIM + k] = l;
}

// ---------------------------------------------------------------------------
// HMMA bf16 GEMM with fp32-split accuracy:
//   C = Ah@Bh^T + Ah@Bl^T + Al@Bh^T (+ bias)
// A[M][256] row-major hi/lo, B[N][256] "col" (K-contiguous) hi/lo.
// CTA 128x128, 8 warps (warp tile 32x64), K-chunk 32, 2-stage smem.
// smem rows padded to 40 bf16 (80 B) -> conflict-free 32-bit frag loads.
// ---------------------------------------------------------------------------
#define KC        32
#define NKCHUNK   (CDIM / KC)                 // 8
#define SROW      40                          // padded row (bf16 elems)
#define TILE_E    (128 * SROW)                // 5120 elems per tile
#define STAGE_E   (4 * TILE_E)                // Ah, Al, Bh, Bl
#define GEMM_SMEM (2 * STAGE_E * 2)           // bytes = 81920

__device__ __forceinline__ void mma_bf16(float* d, const uint32_t* a,
                                         uint32_t b0, uint32_t b1) {
    asm volatile(
        "mma.sync.aligned.m16n8k16.row.col.f32.bf16.bf16.f32 "
        "{%0,%1,%2,%3}, {%4,%5,%6,%7}, {%8,%9}, {%0,%1,%2,%3};"
        : "+f"(d[0]), "+f"(d[1]), "+f"(d[2]), "+f"(d[3])
        : "r"(a[0]), "r"(a[1]), "r"(a[2]), "r"(a[3]), "r"(b0), "r"(b1));
}

template<bool HAS_BIAS>
__global__ void __launch_bounds__(256, 1)
wa3d_mma_gemm(const __nv_bfloat16* __restrict__ Ahi,
              const __nv_bfloat16* __restrict__ Alo,
              const __nv_bfloat16* __restrict__ Bhi,
              const __nv_bfloat16* __restrict__ Blo,
              const float* __restrict__ bias,
              float* __restrict__ C, int Ntot)
{
    extern __shared__ __nv_bfloat16 smem[];   // [2][4][128][40]

    const int tid  = threadIdx.x;
    const int wid  = tid >> 5;
    const int lane = tid & 31;
    const int wm   = wid & 3;                 // 4 m-warps
    const int wn   = wid >> 2;                // 2 n-warps
    const int gr   = lane >> 2;               // fragment row group 0..7
    const int k0   = (lane & 3) << 1;         // fragment k offset (even)

    const int m0 = blockIdx.y * 128;
    const int n0 = blockIdx.x * 128;

    const __nv_bfloat16* gA[2] = { Ahi + (size_t)m0 * CDIM,
                                   Alo + (size_t)m0 * CDIM };
    const __nv_bfloat16* gB[2] = { Bhi + (size_t)n0 * CDIM,
                                   Blo + (size_t)n0 * CDIM };

    float acc[2][8][4];
#pragma unroll
    for (int f = 0; f < 2; ++f)
#pragma unroll
        for (int g = 0; g < 8; ++g)
#pragma unroll
            for (int j = 0; j < 4; ++j) acc[f][g][j] = 0.f;

    // per-thread load slots: 2 float4 per tile, 4 tiles
    const int i0 = tid, i1 = tid + 256;
    const int r0l = i0 >> 2, s0l = i0 & 3;
    const int r1l = i1 >> 2, s1l = i1 & 3;

    float4 pre[8];
    // ---- prefetch chunk 0 ----------------------------------------------
#pragma unroll
    for (int t = 0; t < 2; ++t) {
        pre[t * 2 + 0] = *(const float4*)(gA[t] + (size_t)r0l * CDIM + s0l * 8);
        pre[t * 2 + 1] = *(const float4*)(gA[t] + (size_t)r1l * CDIM + s1l * 8);
        pre[4 + t * 2 + 0] = *(const float4*)(gB[t] + (size_t)r0l * CDIM + s0l * 8);
        pre[4 + t * 2 + 1] = *(const float4*)(gB[t] + (size_t)r1l * CDIM + s1l * 8);
    }
    // store stage 0
#pragma unroll
    for (int t = 0; t < 4; ++t) {
        *(float4*)(smem + t * TILE_E + r0l * SROW + s0l * 8) = pre[t * 2 + 0];
        *(float4*)(smem + t * TILE_E + r1l * SROW + s1l * 8) = pre[t * 2 + 1];
    }
    __syncthreads();

    for (int c = 0; c < NKCHUNK; ++c) {
        const int s = c & 1;
        // prefetch next chunk
        if (c + 1 < NKCHUNK) {
            const int kc = (c + 1) * KC;
#pragma unroll
            for (int t = 0; t < 2; ++t) {
                pre[t * 2 + 0] = *(const float4*)(gA[t] + (size_t)r0l * CDIM + kc + s0l * 8);
                pre[t * 2 + 1] = *(const float4*)(gA[t] + (size_t)r1l * CDIM + kc + s1l * 8);
                pre[4 + t * 2 + 0] = *(const float4*)(gB[t] + (size_t)r0l * CDIM + kc + s0l * 8);
                pre[4 + t * 2 + 1] = *(const float4*)(gB[t] + (size_t)r1l * CDIM + kc + s1l * 8);
            }
        }

        // ---- compute on stage s ---------------------------------------
        const __nv_bfloat16* sAh = smem + s * STAGE_E;
        const __nv_bfloat16* sAl = sAh + TILE_E;
        const __nv_bfloat16* sBh = sAl + TILE_E;
        const __nv_bfloat16* sBl = sBh + TILE_E;

#pragma unroll
        for (int ks = 0; ks < 2; ++ks) {
            const int kb = ks * 16;
            uint32_t ah[2][4], al[2][4];
#pragma unroll
            for (int f = 0; f < 2; ++f) {
                const int row = wm * 32 + f * 16 + gr;
                ah[f][0] = *(const uint32_t*)(sAh + (row)     * SROW + kb + k0);
                ah[f][1] = *(const uint32_t*)(sAh + (row + 8) * SROW + kb + k0);
                ah[f][2] = *(const uint32_t*)(sAh + (row)     * SROW + kb + k0 + 8);
                ah[f][3] = *(const uint32_t*)(sAh + (row + 8) * SROW + kb + k0 + 8);
                al[f][0] = *(const uint32_t*)(sAl + (row)     * SROW + kb + k0);
                al[f][1] = *(const uint32_t*)(sAl + (row + 8) * SROW + kb + k0);
                al[f][2] = *(const uint32_t*)(sAl + (row)     * SROW + kb + k0 + 8);
                al[f][3] = *(const uint32_t*)(sAl + (row + 8) * SROW + kb + k0 + 8);
            }
#pragma unroll
            for (int g = 0; g < 8; ++g) {
                const int cr = wn * 64 + g * 8 + gr;      // B row (= n index)
                uint32_t bh0 = *(const uint32_t*)(sBh + cr * SROW + kb + k0);
                uint32_t bh1 = *(const uint32_t*)(sBh + cr * SROW + kb + k0 + 8);
                uint32_t bl0 = *(const uint32_t*)(sBl + cr * SROW + kb + k0);
                uint32_t bl1 = *(const uint32_t*)(sBl + cr * SROW + kb + k0 + 8);
#pragma unroll
                for (int f = 0; f < 2; ++f) {
                    mma_bf16(acc[f][g], ah[f], bh0, bh1);
                    mma_bf16(acc[f][g], ah[f], bl0, bl1);
                    mma_bf16(acc[f][g], al[f], bh0, bh1);
                }
            }
        }

        // ---- stage next chunk ----------------------------------------
        if (c + 1 < NKCHUNK) {
            __nv_bfloat16* dst = smem + ((c + 1) & 1) * STAGE_E;
#pragma unroll
            for (int t = 0; t < 4; ++t) {
                *(float4*)(dst + t * TILE_E + r0l * SROW + s0l * 8) = pre[t * 2 + 0];
                *(float4*)(dst + t * TILE_E + r1l * SROW + s1l * 8) = pre[t * 2 + 1];
            }
            __syncthreads();
        }
    }

    // ---- epilogue ------------------------------------------------------
#pragma unroll
    for (int f = 0; f < 2; ++f) {
        const int row = m0 + wm * 32 + f * 16 + gr;
#pragma unroll
        for (int g = 0; g < 8; ++g) {
            const int col = n0 + wn * 64 + g * 8 + ((lane & 3) << 1);
            float2 v0 = make_float2(acc[f][g][0], acc[f][g][1]);
            float2 v1 = make_float2(acc[f][g][2], acc[f][g][3]);
            if (HAS_BIAS) {
                float b0 = bias[col], b1 = bias[col + 1];
                v0.x += b0; v0.y += b1;
                v1.x += b0; v1.y += b1;
            }
            *(float2*)(C + (size_t)row * Ntot + col)       = v0;
            *(float2*)(C + (size_t)(row + 8) * Ntot + col) = v1;
        }
    }
}

// ---------------------------------------------------------------------------
// Attention: one CTA per (b, h). 128 threads. Output written as hi/lo bf16.
// ---------------------------------------------------------------------------
#define SC_PITCH 99
#define SC_FLOATS 9704
#define ATTN_SMEM_BYTES ((SC_FLOATS + 2 * NTOK * DH) * 4)   // 63904 B

__global__ void __launch_bounds__(128)
wa3d_attention_kernel(const float* __restrict__ mask)
{
    extern __shared__ float smemf[];
    float*  sc = smemf;                                  // [98][99]
    float4* k4 = (float4*)(smemf + SC_FLOATS);           // [98][8]
    float4* v4 = k4 + NTOK * (DH / 4);                   // [98][8]

    const int bh = blockIdx.x;
    const int b  = bh >> 3;
    const int h  = bh & 7;
    const int w  = b & (NWIN - 1);
    const int tid = threadIdx.x;

    const size_t row_base = (size_t)b * NTOK * QKV_N + h * DH;
    for (int idx = tid; idx < NTOK * (DH / 4); idx += 128) {
        int r = idx >> 3, c = idx & 7;
        const float* kp = g_qkv + row_base + (size_t)r * QKV_N + CDIM + c * 4;
        const float* vp = g_qkv + row_base + (size_t)r * QKV_N + 2 * CDIM + c * 4;
        k4[idx] = *(const float4*)kp;
        v4[idx] = *(const float4*)vp;
    }
    const float* bp = g_bias + h * (NTOK * NTOK);
    const float* mp = mask + (size_t)w * (NTOK * NTOK);
    for (int idx = tid; idx < NTOK * NTOK; idx += 128) {
        int i = idx / NTOK, m = idx - i * NTOK;
        sc[i * SC_PITCH + m] = bp[idx] + mp[idx];
    }
    __syncthreads();

    if (tid < NTOK) {
        const int i = tid;
        float4 q[8];
        const float* qp = g_qkv + row_base + (size_t)i * QKV_N;
#pragma unroll
        for (int c = 0; c < 8; ++c) q[c] = *(const float4*)(qp + c * 4);

        float* srow = sc + i * SC_PITCH;
        for (int m = 0; m < NTOK; ++m) {
            const float4* kr = k4 + m * 8;
            float s = 0.f;
#pragma unroll
            for (int c = 0; c < 8; ++c) {
                float4 kv = kr[c];
                s = fmaf(q[c].x, kv.x, s);
                s = fmaf(q[c].y, kv.y, s);
                s = fmaf(q[c].z, kv.z, s);
                s = fmaf(q[c].w, kv.w, s);
            }
            srow[m] = fmaf(s, SCALE, srow[m]);
        }

        float mx = -1e30f;
        for (int m = 0; m < NTOK; ++m) mx = fmaxf(mx, srow[m]);
        float sum = 0.f;
        for (int m = 0; m < NTOK; ++m) {
            float e = __expf(srow[m] - mx);
            srow[m] = e;
            sum += e;
        }
        const float inv = 1.f / sum;

        float4 o[8];
#pragma unroll
        for (int c = 0; c < 8; ++c) o[c] = make_float4(0.f, 0.f, 0.f, 0.f);
        for (int m = 0; m < NTOK; ++m) {
            const float p = srow[m];
            const float4* vr = v4 + m * 8;
#pragma unroll
            for (int c = 0; c < 8; ++c) {
                float4 vv = vr[c];
                o[c].x = fmaf(p, vv.x, o[c].x);
                o[c].y = fmaf(p, vv.y, o[c].y);
                o[c].z = fmaf(p, vv.z, o[c].z);
                o[c].w = fmaf(p, vv.w, o[c].w);
            }
        }
        const size_t oo = (size_t)(b * NTOK + i) * CDIM + h * DH;
#pragma unroll
        for (int c = 0; c < 8; ++c) {
            union { __nv_bfloat16 bb[4]; uint2 u; } H, L;
            f32_split(o[c].x * inv, H.bb[0], L.bb[0]);
            f32_split(o[c].y * inv, H.bb[1], L.bb[1]);
            f32_split(o[c].z * inv, H.bb[2], L.bb[2]);
            f32_split(o[c].w * inv, H.bb[3], L.bb[3]);
            *(uint2*)(g_aohi + oo + c * 4) = H.u;
            *(uint2*)(g_aolo + oo + c * 4) = L.u;
        }
    }
}

// ---------------------------------------------------------------------------
// Launch
// ---------------------------------------------------------------------------
extern "C" void kernel_launch(void* const* d_in, const int* in_sizes, int n_in,
                              void* d_out, int out_size)
{
    const float* x          = (const float*)d_in[0];
    const float* mask       = (const float*)d_in[1];
    const float* qkv_w      = (const float*)d_in[2];
    const float* proj_w     = (const float*)d_in[3];
    const float* proj_b     = (const float*)d_in[4];
    const float* bias_table = (const float*)d_in[5];
    float* out = (float*)d_out;

    float*         qkv;   cudaGetSymbolAddress((void**)&qkv,   g_qkv);
    __nv_bfloat16* xhi;   cudaGetSymbolAddress((void**)&xhi,   g_xhi);
    __nv_bfloat16* xlo;   cudaGetSymbolAddress((void**)&xlo,   g_xlo);
    __nv_bfloat16* aohi;  cudaGetSymbolAddress((void**)&aohi,  g_aohi);
    __nv_bfloat16* aolo;  cudaGetSymbolAddress((void**)&aolo,  g_aolo);
    __nv_bfloat16* wqh;   cudaGetSymbolAddress((void**)&wqh,   g_wqkv_hi);
    __nv_bfloat16* wql;   cudaGetSymbolAddress((void**)&wql,   g_wqkv_lo);
    __nv_bfloat16* wph;   cudaGetSymbolAddress((void**)&wph,   g_wproj_hi);
    __nv_bfloat16* wpl;   cudaGetSymbolAddress((void**)&wpl,   g_wproj_lo);

    cudaFuncSetAttribute(wa3d_mma_gemm<false>,
                         cudaFuncAttributeMaxDynamicSharedMemorySize, GEMM_SMEM);
    cudaFuncSetAttribute(wa3d_mma_gemm<true>,
                         cudaFuncAttributeMaxDynamicSharedMemorySize, GEMM_SMEM);
    cudaFuncSetAttribute(wa3d_attention_kernel,
                         cudaFuncAttributeMaxDynamicSharedMemorySize, ATTN_SMEM_BYTES);

    // 1. bias table expansion + weight conversion (tiny)
    wa3d_bias_kernel<<<NTOK, 128>>>(bias_table);
    wa3d_cvt_w<<<QKV_N, CDIM>>>(qkv_w, wqh, wql, QKV_N);
    wa3d_cvt_w<<<CDIM, CDIM>>>(proj_w, wph, wpl, CDIM);

    // 2. split x -> hi/lo bf16
    {
        int n4 = MROWS * CDIM / 4;
        wa3d_cvt_split4<<<(n4 + 255) / 256, 256>>>((const float4*)x,
                                                   (uint2*)xhi, (uint2*)xlo, n4);
    }

    // 3. qkv = x @ qkv_w  (HMMA)  [200704,256]x[256,768]
    {
        dim3 grid(QKV_N / 128, MROWS / 128);
        wa3d_mma_gemm<false><<<grid, 256, GEMM_SMEM>>>(xhi, xlo, wqh, wql,
                                                       nullptr, qkv, QKV_N);
    }

    // 4. attention (writes ao hi/lo bf16)
    wa3d_attention_kernel<<<B_TOT * NHEADS, 128, ATTN_SMEM_BYTES>>>(mask);

    // 5. out = attn_out @ proj_w + proj_b  (HMMA) [200704,256]x[256,256]
    {
        dim3 grid(CDIM / 128, MROWS / 128);
        wa3d_mma_gemm<true><<<grid, 256, GEMM_SMEM>>>(aohi, aolo, wph, wpl,
                                                      proj_b, out, CDIM);
    }
}